// round 12
// baseline (speedup 1.0000x reference)
#include <cuda_runtime.h>

#define IMG_H 512
#define IMG_W 512
#define N_IMG 32
#define WS 11
#define HALO 5
#define TS 32
#define TW 42
#define NPART 512

typedef unsigned long long ull;

// Gaussian taps, center at ws/2 = 5.5 (torch quirk): w[k]=w[11-k], w0 unique
#define W0 0.00032030f
#define W1 0.00295565f
#define W2 0.01748763f
#define W3 0.06634246f
#define W4 0.16137298f
#define W5 0.25168106f

__device__ __forceinline__ float wk_of(int k) {
    // compile-time under full unroll -> immediate-form FFMA (rt=1)
    switch (k) {
        case 0: return W0; case 1: return W1; case 2: return W2;
        case 3: return W3; case 4: return W4; case 5: return W5;
        case 6: return W5; case 7: return W4; case 8: return W3;
        case 9: return W2; default: return W1;
    }
}
__device__ __forceinline__ int ksym(int k) { return (k < 6) ? k : (11 - k); } // 6 uniques

__device__ unsigned g_pmin[NPART];
__device__ unsigned g_pmax[NPART];

__device__ __forceinline__ unsigned encf(float f) {
    unsigned u = __float_as_uint(f);
    return (u & 0x80000000u) ? ~u : (u | 0x80000000u);
}
__device__ __forceinline__ float decf(unsigned u) {
    u = (u & 0x80000000u) ? (u & 0x7fffffffu) : ~u;
    return __uint_as_float(u);
}

// ---- packed f32x2 helpers ----
__device__ __forceinline__ ull ffma2(ull a, ull b, ull c) {
    ull d; asm("fma.rn.f32x2 %0, %1, %2, %3;" : "=l"(d) : "l"(a), "l"(b), "l"(c)); return d;
}
__device__ __forceinline__ ull fmul2(ull a, ull b) {
    ull d; asm("mul.rn.f32x2 %0, %1, %2;" : "=l"(d) : "l"(a), "l"(b)); return d;
}
__device__ __forceinline__ ull pk2(float lo, float hi) {
    ull d; asm("mov.b64 %0, {%1, %2};" : "=l"(d) : "f"(lo), "f"(hi)); return d;
}
__device__ __forceinline__ float2 upk(ull v) {
    float2 r; asm("mov.b64 {%0, %1}, %2;" : "=f"(r.x), "=f"(r.y) : "l"(v)); return r;
}

__global__ __launch_bounds__(256)
void minmax_kernel(const float* __restrict__ x, int n4) {
    unsigned mn = 0xFFFFFFFFu, mx = 0u;
    const float4* x4 = (const float4*)x;
    for (int i = blockIdx.x * blockDim.x + threadIdx.x; i < n4;
         i += gridDim.x * blockDim.x) {
        float4 v = x4[i];
        unsigned e0 = encf(v.x), e1 = encf(v.y), e2 = encf(v.z), e3 = encf(v.w);
        mn = min(mn, min(min(e0, e1), min(e2, e3)));
        mx = max(mx, max(max(e0, e1), max(e2, e3)));
    }
    #pragma unroll
    for (int off = 16; off > 0; off >>= 1) {
        mn = min(mn, __shfl_xor_sync(0xFFFFFFFFu, mn, off));
        mx = max(mx, __shfl_xor_sync(0xFFFFFFFFu, mx, off));
    }
    __shared__ unsigned smn[8], smx[8];
    int wid = threadIdx.x >> 5, lid = threadIdx.x & 31;
    if (lid == 0) { smn[wid] = mn; smx[wid] = mx; }
    __syncthreads();
    if (threadIdx.x == 0) {
        unsigned bmn = smn[0], bmx = smx[0];
        #pragma unroll
        for (int i = 1; i < 8; i++) { bmn = min(bmn, smn[i]); bmx = max(bmx, smx[i]); }
        g_pmin[blockIdx.x] = bmn;
        g_pmax[blockIdx.x] = bmx;
    }
    asm volatile("griddepcontrol.launch_dependents;" ::: "memory");
}

struct HAcc2 { ull p01[4], p23[4]; float s4[4]; };

__device__ __forceinline__ void consume2(HAcc2& s, const ull* WP, int e, float a, float b) {
    ull pab  = pk2(a, b);
    ull pab2 = fmul2(pab, pab);   // (a*a, b*b)
    float ab = a * b;
    #pragma unroll
    for (int j = 0; j < 4; j++) {
        int k = e - 3 - j;
        if (k >= 0 && k < WS) {
            ull w = WP[ksym(k)];
            s.p01[j] = ffma2(pab,  w, s.p01[j]);   // (mu1, mu2) partials
            s.p23[j] = ffma2(pab2, w, s.p23[j]);   // (E[a^2], E[b^2]) partials
            s.s4[j]  = fmaf(wk_of(k), ab, s.s4[j]); // E[ab] partial, imm-form
        }
    }
}

__device__ __forceinline__ void hproc(
    int r, int c0, int x0, int y0,
    const float* __restrict__ p1, const float* __restrict__ p2,
    bool interior, const ull* WP,
    ull (&h01)[TW][TS], ull (&h23)[TW][TS], float (&h4)[TW][TS])
{
    HAcc2 s;
    #pragma unroll
    for (int j = 0; j < 4; j++) { s.p01[j] = 0; s.p23[j] = 0; s.s4[j] = 0.f; }
    const int gy = y0 + r - HALO;
    // needed positions: e = 3..16, global col = x0 + c0 - 8 + e
    if (interior) {
        const float4* r1 = (const float4*)(p1 + (long)gy * IMG_W + (x0 + c0 - 8));
        const float4* r2 = (const float4*)(p2 + (long)gy * IMG_W + (x0 + c0 - 8));
        #pragma unroll
        for (int t = 0; t < 5; t++) {
            float4 va = __ldg(r1 + t);
            float4 vb = __ldg(r2 + t);
            const int e = 4 * t;
            if (e + 0 >= 3 && e + 0 <= 16) consume2(s, WP, e + 0, va.x, vb.x);
            if (e + 1 >= 3 && e + 1 <= 16) consume2(s, WP, e + 1, va.y, vb.y);
            if (e + 2 >= 3 && e + 2 <= 16) consume2(s, WP, e + 2, va.z, vb.z);
            if (e + 3 >= 3 && e + 3 <= 16) consume2(s, WP, e + 3, va.w, vb.w);
        }
    } else {
        const bool yok = (gy >= 0) & (gy < IMG_H);
        const float* b1 = p1 + (long)gy * IMG_W;
        const float* b2 = p2 + (long)gy * IMG_W;
        #pragma unroll
        for (int e = 3; e <= 16; e++) {
            int gx = x0 + c0 - 8 + e;
            bool ok = yok & (gx >= 0) & (gx < IMG_W);
            float a = 0.f, b = 0.f;
            if (ok) { a = __ldg(b1 + gx); b = __ldg(b2 + gx); }
            consume2(s, WP, e, a, b);
        }
    }
    *(ulonglong2*)&h01[r][c0]     = make_ulonglong2(s.p01[0], s.p01[1]);
    *(ulonglong2*)&h01[r][c0 + 2] = make_ulonglong2(s.p01[2], s.p01[3]);
    *(ulonglong2*)&h23[r][c0]     = make_ulonglong2(s.p23[0], s.p23[1]);
    *(ulonglong2*)&h23[r][c0 + 2] = make_ulonglong2(s.p23[2], s.p23[3]);
    *(float4*)&h4[r][c0] = make_float4(s.s4[0], s.s4[1], s.s4[2], s.s4[3]);
}

__global__ __launch_bounds__(256, 4)
void ssim_kernel(const float* __restrict__ img1, const float* __restrict__ img2,
                 float* __restrict__ out) {
    __shared__ ull   h01[TW][TS];   // packed (mean_a, mean_b) partials
    __shared__ ull   h23[TW][TS];   // packed (E[a^2], E[b^2]) partials
    __shared__ float h4[TW][TS];    // E[ab] partials
    __shared__ unsigned red_mn[8], red_mx[8];

    const int n = blockIdx.z;
    const int x0 = blockIdx.x * TS;
    const int y0 = blockIdx.y * TS;
    const int tid = threadIdx.x;

    // 6 unique broadcast weight pairs in registers
    ull WP[6];
    WP[0] = pk2(W0, W0); WP[1] = pk2(W1, W1); WP[2] = pk2(W2, W2);
    WP[3] = pk2(W3, W3); WP[4] = pk2(W4, W4); WP[5] = pk2(W5, W5);

    const float* p1 = img1 + (size_t)n * IMG_H * IMG_W;
    const float* p2 = img2 + (size_t)n * IMG_H * IMG_W;

    const bool interior = (x0 != 0) & (x0 != IMG_W - TS) &
                          (y0 != 0) & (y0 != IMG_H - TS);

    // ---- horizontal pass straight from global ----
    {
        int r = tid >> 3;
        int c0 = (tid & 7) << 2;
        hproc(r, c0, x0, y0, p1, p2, interior, WP, h01, h23, h4);
        if (tid < 80) hproc(r + 32, c0, x0, y0, p1, p2, interior, WP, h01, h23, h4);
    }
    __syncthreads();

    // ---- vertical pass: 4 adjacent output rows per thread, field-packed ----
    const int tx = tid & 31;
    const int ty0 = (tid >> 5) << 2;   // 0,4,...,28
    ull a01[4] = {0,0,0,0}, a23[4] = {0,0,0,0};
    float a4[4] = {0,0,0,0};
    #pragma unroll
    for (int i = 0; i < 14; i++) {
        ull v01 = h01[ty0 + i][tx];
        ull v23 = h23[ty0 + i][tx];
        float v4 = h4[ty0 + i][tx];
        #pragma unroll
        for (int j = 0; j < 4; j++) {
            int k = i - j;
            if (k >= 0 && k < WS) {
                ull w = WP[ksym(k)];
                a01[j] = ffma2(v01, w, a01[j]);
                a23[j] = ffma2(v23, w, a23[j]);
                a4[j]  = fmaf(wk_of(k), v4, a4[j]);
            }
        }
    }

    // ---- PDL: minmax results only needed from here ----
    asm volatile("griddepcontrol.wait;" ::: "memory");
    {
        unsigned mn = min(g_pmin[tid], g_pmin[tid + 256]);
        unsigned mx = max(g_pmax[tid], g_pmax[tid + 256]);
        #pragma unroll
        for (int off = 16; off > 0; off >>= 1) {
            mn = min(mn, __shfl_xor_sync(0xFFFFFFFFu, mn, off));
            mx = max(mx, __shfl_xor_sync(0xFFFFFFFFu, mx, off));
        }
        if ((tid & 31) == 0) { red_mn[tid >> 5] = mn; red_mx[tid >> 5] = mx; }
    }
    __syncthreads();

    float C1, C2;
    {
        unsigned bmn = red_mn[0], bmx = red_mx[0];
        #pragma unroll
        for (int i = 1; i < 8; i++) { bmn = min(bmn, red_mn[i]); bmx = max(bmx, red_mx[i]); }
        float L = decf(bmx) - decf(bmn);
        if (L == 0.f) L = 5.f;
        C1 = (0.01f * L) * (0.01f * L);
        C2 = (0.03f * L) * (0.03f * L);
    }

    float* po = out + (size_t)n * IMG_H * IMG_W;
    #pragma unroll
    for (int j = 0; j < 4; j++) {
        float2 m = upk(a01[j]);    // (mu1, mu2)
        float2 q = upk(a23[j]);    // (E[a^2], E[b^2])
        float mu1_sq = m.x * m.x;
        float mu2_sq = m.y * m.y;
        float mu1mu2 = m.x * m.y;
        float sig1  = q.x   - mu1_sq;
        float sig2  = q.y   - mu2_sq;
        float sig12 = a4[j] - mu1mu2;
        float num = (2.f * mu1mu2 + C1) * (2.f * sig12 + C2);
        float den = (mu1_sq + mu2_sq + C1) * (sig1 + sig2 + C2);
        po[(size_t)(y0 + ty0 + j) * IMG_W + (x0 + tx)] = __fdividef(num, den);
    }
}

extern "C" void kernel_launch(void* const* d_in, const int* in_sizes, int n_in,
                              void* d_out, int out_size) {
    const float* img1 = (const float*)d_in[0];
    const float* img2 = (const float*)d_in[1];
    float* out = (float*)d_out;

    int n_elems = N_IMG * IMG_H * IMG_W;
    minmax_kernel<<<NPART, 256>>>(img1, n_elems / 4);

    cudaLaunchConfig_t cfg = {};
    cfg.gridDim = dim3(IMG_W / TS, IMG_H / TS, N_IMG);
    cfg.blockDim = dim3(256, 1, 1);
    cfg.dynamicSmemBytes = 0;
    cfg.stream = 0;
    cudaLaunchAttribute at[1];
    at[0].id = cudaLaunchAttributeProgrammaticStreamSerialization;
    at[0].val.programmaticStreamSerializationAllowed = 1;
    cfg.attrs = at;
    cfg.numAttrs = 1;
    cudaLaunchKernelEx(&cfg, ssim_kernel, img1, img2, out);
}

// round 13
// speedup vs baseline: 1.0261x; 1.0261x over previous
#include <cuda_runtime.h>

#define IMG_H 512
#define IMG_W 512
#define N_IMG 32
#define WS 11
#define HALO 5
#define TSX 64
#define TSY 32
#define TW 42            // TSY + 2*HALO
#define NPART 512

// Gaussian taps, center at ws/2 = 5.5 (torch quirk): w[k]=w[11-k], w0 unique
#define W0 0.00032030f
#define W1 0.00295565f
#define W2 0.01748763f
#define W3 0.06634246f
#define W4 0.16137298f
#define W5 0.25168106f

__device__ __forceinline__ float wk_of(int k) {
    // compile-time under full unroll -> immediate-form FFMA (rt=1)
    switch (k) {
        case 0: return W0; case 1: return W1; case 2: return W2;
        case 3: return W3; case 4: return W4; case 5: return W5;
        case 6: return W5; case 7: return W4; case 8: return W3;
        case 9: return W2; default: return W1;
    }
}

__device__ unsigned g_pmin[NPART];
__device__ unsigned g_pmax[NPART];

__device__ __forceinline__ unsigned encf(float f) {
    unsigned u = __float_as_uint(f);
    return (u & 0x80000000u) ? ~u : (u | 0x80000000u);
}
__device__ __forceinline__ float decf(unsigned u) {
    u = (u & 0x80000000u) ? (u & 0x7fffffffu) : ~u;
    return __uint_as_float(u);
}

__global__ __launch_bounds__(256)
void minmax_kernel(const float* __restrict__ x, int n4) {
    unsigned mn = 0xFFFFFFFFu, mx = 0u;
    const float4* x4 = (const float4*)x;
    for (int i = blockIdx.x * blockDim.x + threadIdx.x; i < n4;
         i += gridDim.x * blockDim.x) {
        float4 v = x4[i];
        unsigned e0 = encf(v.x), e1 = encf(v.y), e2 = encf(v.z), e3 = encf(v.w);
        mn = min(mn, min(min(e0, e1), min(e2, e3)));
        mx = max(mx, max(max(e0, e1), max(e2, e3)));
    }
    #pragma unroll
    for (int off = 16; off > 0; off >>= 1) {
        mn = min(mn, __shfl_xor_sync(0xFFFFFFFFu, mn, off));
        mx = max(mx, __shfl_xor_sync(0xFFFFFFFFu, mx, off));
    }
    __shared__ unsigned smn[8], smx[8];
    int wid = threadIdx.x >> 5, lid = threadIdx.x & 31;
    if (lid == 0) { smn[wid] = mn; smx[wid] = mx; }
    __syncthreads();
    if (threadIdx.x == 0) {
        unsigned bmn = smn[0], bmx = smx[0];
        #pragma unroll
        for (int i = 1; i < 8; i++) { bmn = min(bmn, smn[i]); bmx = max(bmx, smx[i]); }
        g_pmin[blockIdx.x] = bmn;
        g_pmax[blockIdx.x] = bmx;
    }
    asm volatile("griddepcontrol.launch_dependents;" ::: "memory");
}

struct HAcc { float f0[4], f1[4], f2[4], f3[4], f4[4]; };

__device__ __forceinline__ void consume(HAcc& s, int e, float a, float b) {
    float aa = a * a, bb = b * b, ab = a * b;
    #pragma unroll
    for (int j = 0; j < 4; j++) {
        int k = e - 3 - j;           // tap index for output j
        if (k >= 0 && k < WS) {
            float w = wk_of(k);
            s.f0[j] = fmaf(w, a,  s.f0[j]);
            s.f1[j] = fmaf(w, b,  s.f1[j]);
            s.f2[j] = fmaf(w, aa, s.f2[j]);
            s.f3[j] = fmaf(w, bb, s.f3[j]);
            s.f4[j] = fmaf(w, ab, s.f4[j]);
        }
    }
}

#define HIDX(f, r, c) (((f) * TW + (r)) * TSX + (c))

// Horizontal pass for one item: 4 outputs (tile cols c0..c0+3) on tile row r,
// reading img directly from global.
__device__ __forceinline__ void hproc(
    int item, int x0, int y0,
    const float* __restrict__ p1, const float* __restrict__ p2,
    bool interior, float* __restrict__ h)
{
    const int r  = item >> 4;          // 0..41
    const int c0 = (item & 15) << 2;   // 0..60
    HAcc s;
    #pragma unroll
    for (int j = 0; j < 4; j++) {
        s.f0[j] = 0.f; s.f1[j] = 0.f; s.f2[j] = 0.f; s.f3[j] = 0.f; s.f4[j] = 0.f;
    }
    const int gy = y0 + r - HALO;
    // needed positions: e = 3..16, global col = x0 + c0 - 8 + e
    if (interior) {
        const float4* r1 = (const float4*)(p1 + (long)gy * IMG_W + (x0 + c0 - 8));
        const float4* r2 = (const float4*)(p2 + (long)gy * IMG_W + (x0 + c0 - 8));
        #pragma unroll
        for (int t = 0; t < 5; t++) {
            float4 va = __ldg(r1 + t);
            float4 vb = __ldg(r2 + t);
            const int e = 4 * t;
            if (e + 0 >= 3 && e + 0 <= 16) consume(s, e + 0, va.x, vb.x);
            if (e + 1 >= 3 && e + 1 <= 16) consume(s, e + 1, va.y, vb.y);
            if (e + 2 >= 3 && e + 2 <= 16) consume(s, e + 2, va.z, vb.z);
            if (e + 3 >= 3 && e + 3 <= 16) consume(s, e + 3, va.w, vb.w);
        }
    } else {
        const bool yok = (gy >= 0) & (gy < IMG_H);
        const float* b1 = p1 + (long)gy * IMG_W;
        const float* b2 = p2 + (long)gy * IMG_W;
        #pragma unroll
        for (int e = 3; e <= 16; e++) {
            int gx = x0 + c0 - 8 + e;
            bool ok = yok & (gx >= 0) & (gx < IMG_W);
            float a = 0.f, b = 0.f;
            if (ok) { a = __ldg(b1 + gx); b = __ldg(b2 + gx); }
            consume(s, e, a, b);
        }
    }
    *(float4*)&h[HIDX(0, r, c0)] = make_float4(s.f0[0], s.f0[1], s.f0[2], s.f0[3]);
    *(float4*)&h[HIDX(1, r, c0)] = make_float4(s.f1[0], s.f1[1], s.f1[2], s.f1[3]);
    *(float4*)&h[HIDX(2, r, c0)] = make_float4(s.f2[0], s.f2[1], s.f2[2], s.f2[3]);
    *(float4*)&h[HIDX(3, r, c0)] = make_float4(s.f3[0], s.f3[1], s.f3[2], s.f3[3]);
    *(float4*)&h[HIDX(4, r, c0)] = make_float4(s.f4[0], s.f4[1], s.f4[2], s.f4[3]);
}

__global__ __launch_bounds__(256)
void ssim_kernel(const float* __restrict__ img1, const float* __restrict__ img2,
                 float* __restrict__ out) {
    extern __shared__ float h[];               // 5 * TW * TSX floats
    __shared__ unsigned red_mn[8], red_mx[8];

    const int n = blockIdx.z;
    const int x0 = blockIdx.x * TSX;
    const int y0 = blockIdx.y * TSY;
    const int tid = threadIdx.x;

    const float* p1 = img1 + (size_t)n * IMG_H * IMG_W;
    const float* p2 = img2 + (size_t)n * IMG_H * IMG_W;

    const bool interior = (x0 != 0) & (x0 != IMG_W - TSX) &
                          (y0 != 0) & (y0 != IMG_H - TSY);

    // ---- horizontal pass straight from global: 672 items, <=3 per thread ----
    hproc(tid,       x0, y0, p1, p2, interior, h);
    hproc(tid + 256, x0, y0, p1, p2, interior, h);
    if (tid < 160) hproc(tid + 512, x0, y0, p1, p2, interior, h);
    __syncthreads();

    // ---- PDL: minmax certainly finished during horizontal phase ----
    asm volatile("griddepcontrol.wait;" ::: "memory");
    {
        unsigned mn = min(g_pmin[tid], g_pmin[tid + 256]);
        unsigned mx = max(g_pmax[tid], g_pmax[tid + 256]);
        #pragma unroll
        for (int off = 16; off > 0; off >>= 1) {
            mn = min(mn, __shfl_xor_sync(0xFFFFFFFFu, mn, off));
            mx = max(mx, __shfl_xor_sync(0xFFFFFFFFu, mx, off));
        }
        if ((tid & 31) == 0) { red_mn[tid >> 5] = mn; red_mx[tid >> 5] = mx; }
    }
    __syncthreads();

    float C1, C2;
    {
        unsigned bmn = red_mn[0], bmx = red_mx[0];
        #pragma unroll
        for (int i = 1; i < 8; i++) { bmn = min(bmn, red_mn[i]); bmx = max(bmx, red_mx[i]); }
        float L = decf(bmx) - decf(bmn);
        if (L == 0.f) L = 5.f;
        C1 = (0.01f * L) * (0.01f * L);
        C2 = (0.03f * L) * (0.03f * L);
    }

    // ---- vertical pass: 2 items x 4 adjacent rows, exactly 2 per thread ----
    const int tx  = tid & 63;
    const int tyb = (tid >> 6) << 2;   // 0,4,8,12
    float* po = out + (size_t)n * IMG_H * IMG_W;

    #pragma unroll
    for (int it = 0; it < 2; it++) {
        const int ty0 = tyb + it * 16;   // 0..28
        float m1[4]  = {0,0,0,0}, m2[4]  = {0,0,0,0};
        float q1[4]  = {0,0,0,0}, q2a[4] = {0,0,0,0}, q12[4] = {0,0,0,0};
        #pragma unroll
        for (int i = 0; i < 14; i++) {
            float v0 = h[HIDX(0, ty0 + i, tx)];
            float v1 = h[HIDX(1, ty0 + i, tx)];
            float v2 = h[HIDX(2, ty0 + i, tx)];
            float v3 = h[HIDX(3, ty0 + i, tx)];
            float v4 = h[HIDX(4, ty0 + i, tx)];
            #pragma unroll
            for (int j = 0; j < 4; j++) {
                int k = i - j;
                if (k >= 0 && k < WS) {
                    float w = wk_of(k);
                    m1[j]  = fmaf(w, v0, m1[j]);
                    m2[j]  = fmaf(w, v1, m2[j]);
                    q1[j]  = fmaf(w, v2, q1[j]);
                    q2a[j] = fmaf(w, v3, q2a[j]);
                    q12[j] = fmaf(w, v4, q12[j]);
                }
            }
        }
        #pragma unroll
        for (int j = 0; j < 4; j++) {
            float mu1_sq = m1[j] * m1[j];
            float mu2_sq = m2[j] * m2[j];
            float mu1mu2 = m1[j] * m2[j];
            float sig1  = q1[j]  - mu1_sq;
            float sig2  = q2a[j] - mu2_sq;
            float sig12 = q12[j] - mu1mu2;
            float num = (2.f * mu1mu2 + C1) * (2.f * sig12 + C2);
            float den = (mu1_sq + mu2_sq + C1) * (sig1 + sig2 + C2);
            po[(size_t)(y0 + ty0 + j) * IMG_W + (x0 + tx)] = __fdividef(num, den);
        }
    }
}

extern "C" void kernel_launch(void* const* d_in, const int* in_sizes, int n_in,
                              void* d_out, int out_size) {
    const float* img1 = (const float*)d_in[0];
    const float* img2 = (const float*)d_in[1];
    float* out = (float*)d_out;

    const int hbytes = 5 * TW * TSX * (int)sizeof(float);   // 53760 B
    cudaFuncSetAttribute(ssim_kernel,
                         cudaFuncAttributeMaxDynamicSharedMemorySize, hbytes);

    int n_elems = N_IMG * IMG_H * IMG_W;
    minmax_kernel<<<NPART, 256>>>(img1, n_elems / 4);

    cudaLaunchConfig_t cfg = {};
    cfg.gridDim = dim3(IMG_W / TSX, IMG_H / TSY, N_IMG);
    cfg.blockDim = dim3(256, 1, 1);
    cfg.dynamicSmemBytes = hbytes;
    cfg.stream = 0;
    cudaLaunchAttribute at[1];
    at[0].id = cudaLaunchAttributeProgrammaticStreamSerialization;
    at[0].val.programmaticStreamSerializationAllowed = 1;
    cfg.attrs = at;
    cfg.numAttrs = 1;
    cudaLaunchKernelEx(&cfg, ssim_kernel, img1, img2, out);
}